// round 17
// baseline (speedup 1.0000x reference)
#include <cuda_runtime.h>
#include <cuda_fp16.h>
#include <stdint.h>
#include <math.h>

#define S_SAMPLES 10
#define IN_DIM    512
#define HID_DIM   1024
#define OUT_DIM   512
#define BATCH     1024
#define NPARAMS   (HID_DIM*IN_DIM + OUT_DIM*HID_DIM)   // 1,048,576
#define N1        (HID_DIM*IN_DIM)                      // 524,288

// Tile geometry: 64(M) x 128(N) CTA tile, warp tile 32x32 (2M x 4N warps).
#define L1_TILES_PER_S ((BATCH/64) * (HID_DIM/128))   // 128
#define L2_TILES_PER_S ((BATCH/64) * (OUT_DIM/128))   // 64
#define L1_CTAS (S_SAMPLES * L1_TILES_PER_S)          // 1280
#define L2_CTAS (S_SAMPLES * L2_TILES_PER_S)          // 640

// ---------------------------------------------------------------------------
// Scratch (device globals — no allocation allowed)
// Full fp16 path (measured rel_err 4.2e-4 < 1e-3).
// ---------------------------------------------------------------------------
static __device__ float g_hm[S_SAMPLES * 10];
static __device__ int   g_cnt[S_SAMPLES];
static __device__ __half g_xh[BATCH * IN_DIM];
static __device__ __half g_th[(size_t)S_SAMPLES * NPARAMS];
static __device__ __half g_ah[(size_t)S_SAMPLES * BATCH * HID_DIM];

__device__ __forceinline__ float elu1(float v) { return v > 0.0f ? v : expm1f(v); }

// ---------------------------------------------------------------------------
// PTX helpers (portable: sm_80+ instructions only)
// ---------------------------------------------------------------------------
__device__ __forceinline__ uint32_t smem_u32(const void* p) {
    uint32_t a;
    asm("{ .reg .u64 t; cvta.to.shared.u64 t, %1; cvt.u32.u64 %0, t; }" : "=r"(a) : "l"(p));
    return a;
}
__device__ __forceinline__ void cp_async16(uint32_t smem_dst, const void* gmem_src) {
    asm volatile("cp.async.cg.shared.global [%0], [%1], 16;"
                 :: "r"(smem_dst), "l"(gmem_src));
}
__device__ __forceinline__ void cp_commit() {
    asm volatile("cp.async.commit_group;");
}
__device__ __forceinline__ void cp_wait0() {
    asm volatile("cp.async.wait_group 0;");
}
__device__ __forceinline__ void ldsm4(uint32_t* r, uint32_t addr) {
    asm volatile("ldmatrix.sync.aligned.m8n8.x4.shared.b16 {%0,%1,%2,%3}, [%4];"
                 : "=r"(r[0]), "=r"(r[1]), "=r"(r[2]), "=r"(r[3]) : "r"(addr));
}
__device__ __forceinline__ void mma16816(float* d, const uint32_t* a, const uint32_t* b) {
    asm volatile("mma.sync.aligned.m16n8k16.row.col.f32.f16.f16.f32 "
                 "{%0,%1,%2,%3}, {%4,%5,%6,%7}, {%8,%9}, {%0,%1,%2,%3};"
                 : "+f"(d[0]), "+f"(d[1]), "+f"(d[2]), "+f"(d[3])
                 : "r"(a[0]), "r"(a[1]), "r"(a[2]), "r"(a[3]), "r"(b[0]), "r"(b[1]));
}

// ---------------------------------------------------------------------------
// Kernel 1: tiny hypernet trunk
// ---------------------------------------------------------------------------
__global__ void hyper_trunk_kernel(const float* __restrict__ z,
                                   const float* __restrict__ Wa,
                                   const float* __restrict__ Wb) {
    __shared__ float h1[S_SAMPLES * 10];
    int tid = threadIdx.x;
    if (tid < S_SAMPLES * 10) {
        int s = tid / 10, w = tid % 10;
        float acc = 0.0f;
        #pragma unroll
        for (int c = 0; c < 8; c++) acc += z[s*8 + c] * Wa[w*8 + c];
        h1[tid] = elu1(acc);
    }
    __syncthreads();
    if (tid < S_SAMPLES * 10) {
        int s = tid / 10, v = tid % 10;
        float acc = 0.0f;
        #pragma unroll
        for (int w = 0; w < 10; w++) acc += h1[s*10 + w] * Wb[v*10 + w];
        g_hm[s*10 + v] = elu1(acc);
    }
}

// ---------------------------------------------------------------------------
// Kernel 2: x -> single fp16
// ---------------------------------------------------------------------------
__global__ void xconv_kernel(const float* __restrict__ x) {
    int i4 = blockIdx.x * blockDim.x + threadIdx.x;
    if (i4 * 4 >= BATCH * IN_DIM) return;
    float4 v = reinterpret_cast<const float4*>(x)[i4];
    __half2 h01 = __halves2half2(__float2half_rn(v.x), __float2half_rn(v.y));
    __half2 h23 = __halves2half2(__float2half_rn(v.z), __float2half_rn(v.w));
    reinterpret_cast<uint2*>(g_xh)[i4] = make_uint2(*(uint32_t*)&h01, *(uint32_t*)&h23);
}

// ---------------------------------------------------------------------------
// Kernel 3: theta -> single fp16. Also zeroes layer1-completion counters.
// ---------------------------------------------------------------------------
__global__ void theta_kernel(const float* __restrict__ Wc) {
    if (blockIdx.x == 0 && threadIdx.x < S_SAMPLES) g_cnt[threadIdx.x] = 0;

    __shared__ float hm_s[S_SAMPLES * 10];
    if (threadIdx.x < S_SAMPLES * 10) hm_s[threadIdx.x] = g_hm[threadIdx.x];
    __syncthreads();

    int p0 = (blockIdx.x * blockDim.x + threadIdx.x) * 2;
    if (p0 >= NPARAMS) return;

    float wc0[10], wc1[10];
    #pragma unroll
    for (int v = 0; v < 10; v++) {
        wc0[v] = Wc[(size_t)p0 * 10 + v];
        wc1[v] = Wc[(size_t)(p0 + 1) * 10 + v];
    }
    #pragma unroll
    for (int s = 0; s < S_SAMPLES; s++) {
        float a0 = 0.0f, a1 = 0.0f;
        #pragma unroll
        for (int v = 0; v < 10; v++) {
            a0 += hm_s[s*10 + v] * wc0[v];
            a1 += hm_s[s*10 + v] * wc1[v];
        }
        __half2 hp = __halves2half2(__float2half_rn(a0), __float2half_rn(a1));
        *reinterpret_cast<uint32_t*>(g_th + (size_t)s * NPARAMS + p0) = *(uint32_t*)&hp;
    }
}

// ---------------------------------------------------------------------------
// Fused GEMM kernel: one flat grid of 1920 CTAs.
//   bx in [0, 1280):    layer1 tile — a[s] = elu(x @ W1[s]^T), K=512 (8 chunks)
//   bx in [1280, 1920): layer2 tile — y[s] = a[s] @ W2[s]^T,  K=1024 (16 chunks)
// Layer2 CTAs spin on g_cnt[s]==128 before their first load (deadlock-free by
// linear dispatch order).
//
// GEMM body: mma.sync NT full fp16, 64x128 CTA tile, 8 warps (2Mx4N),
// warp tile 32x32. KC=64 (was 32): with 1 MMA per product the per-chunk
// fixed costs (barrier, cp_wait drain, ldsm latency) dominated at 34.5%
// tensor — doubling the chunk halves them per MMA. 2-stage cp.async,
// one __syncthreads per chunk, 3 CTAs/SM.
// SMS=72: 144B row stride — 16B-multiple (cp.async) and conflict-free
// ldmatrix (36*r mod 32 distinct over 8 rows).
// Stage = (64 A + 128 B) rows * 144B = 27648B; 2 stages = 55296B/CTA.
// ---------------------------------------------------------------------------
#define KC      64
#define SMS     72
#define TA_E    (64 * SMS)               // A tile elems (4608)
#define TB_E    (128 * SMS)              // B tile elems (9216)
#define STAGE_B ((TA_E + TB_E) * 2)      // 27648 B
#define SMEM_BYTES (2 * STAGE_B)         // 55296
#define OFF_B   (TA_E * 2)

__global__ __launch_bounds__(256, 3)
void fused_gemm_kernel(const __half* __restrict__ xh,
                       const __half* __restrict__ th,
                       __half* __restrict__ ah,
                       float* __restrict__ out) {
    extern __shared__ __half sm[];
    const uint32_t smb = smem_u32(sm);
    const int tid  = threadIdx.x;
    const int lane = tid & 31, wid = tid >> 5;
    const int warpM = wid & 1, warpN = wid >> 1;   // 2M x 4N
    const int bx = blockIdx.x;
    const bool L1 = bx < L1_CTAS;

    int s, m0, n0, lda, ldb, ldc, NC;
    const __half *Ah_, *Bh_;
    __half *Ch = nullptr;
    float* Cf = nullptr;

    if (L1) {
        s = bx / L1_TILES_PER_S;
        int t = bx % L1_TILES_PER_S;
        m0 = (t >> 3) * 64;  n0 = (t & 7) * 128;
        Ah_ = xh;  lda = IN_DIM;
        Bh_ = th + (size_t)s * NPARAMS;  ldb = IN_DIM;
        Ch = ah + (size_t)s * BATCH * HID_DIM;
        ldc = HID_DIM;  NC = IN_DIM / KC;      // 8
    } else {
        int idx = bx - L1_CTAS;
        s = idx / L2_TILES_PER_S;
        int t = idx % L2_TILES_PER_S;
        m0 = (t >> 2) * 64;  n0 = (t & 3) * 128;
        Ah_ = ah + (size_t)s * BATCH * HID_DIM;  lda = HID_DIM;
        Bh_ = th + (size_t)s * NPARAMS + N1;     ldb = HID_DIM;
        Cf = out + (size_t)s * BATCH * OUT_DIM;
        ldc = OUT_DIM;  NC = HID_DIM / KC;       // 16

        // Wait for this sample's layer1 to complete before any load.
        if (tid == 0) {
            while (*(volatile int*)&g_cnt[s] < L1_TILES_PER_S) __nanosleep(128);
        }
        __syncthreads();
        __threadfence();   // acquire: order subsequent loads after the flag read
    }

    // Producer mapping (KC=64 elems per row).
    // A: 256 threads cover 64 rows x 4 col-chunks of 16 elems; 2 cp16 each.
    const int par = tid >> 2;               // 0..63
    const int pav = (tid & 3) * 16;         // 0,16,32,48
    const __half* pAh = Ah_ + (size_t)(m0 + par) * lda + pav;
    const uint32_t pdA = smb + (uint32_t)(par * SMS + pav) * 2;
    // B: 256 threads cover 128 rows x 2 halves of 32 elems; 4 cp16 each.
    const int pbr = tid >> 1;               // 0..127
    const int pbv = (tid & 1) * 32;         // 0 or 32
    const __half* pBh = Bh_ + (size_t)(n0 + pbr) * ldb + pbv;
    const uint32_t pdB = smb + (uint32_t)(pbr * SMS + pbv) * 2;

    // Consumer (ldmatrix) base addresses, hoisted.
    const uint32_t aOff = smb + (uint32_t)(((warpM * 32 + (lane & 15)) * SMS
                                            + ((lane >> 4) << 3)) * 2);
    const int rr = (lane & 7) + ((lane >> 4) & 1) * 8;
    const int kh = (lane >> 3) & 1;
    const uint32_t bOff = smb + OFF_B
                        + (uint32_t)(((warpN * 32 + rr) * SMS + kh * 8) * 2);

    float acc[2][4][4];
    #pragma unroll
    for (int i = 0; i < 2; i++)
        #pragma unroll
        for (int j = 0; j < 4; j++)
            #pragma unroll
            for (int q = 0; q < 4; q++) acc[i][j][q] = 0.0f;

    auto issue = [&](int stage, int k0) {
        const uint32_t so = (uint32_t)stage * STAGE_B;
        cp_async16(pdA + so,      pAh + k0);
        cp_async16(pdA + so + 16, pAh + k0 + 8);
        #pragma unroll
        for (int v = 0; v < 32; v += 8)
            cp_async16(pdB + so + OFF_B + v * 2, pBh + k0 + v);
        cp_commit();
    };

    issue(0, 0);

    for (int c = 0; c < NC; c++) {
        cp_wait0();
        __syncthreads();
        if (c + 1 < NC) issue((c + 1) & 1, (c + 1) * KC);

        const uint32_t aB = aOff + (uint32_t)(c & 1) * STAGE_B;
        const uint32_t bB = bOff + (uint32_t)(c & 1) * STAGE_B;
        #pragma unroll
        for (int ks = 0; ks < 4; ks++) {
            uint32_t af[2][4];
            #pragma unroll
            for (int i = 0; i < 2; i++) {
                uint32_t off = (uint32_t)((i * 16 * SMS + ks * 16) * 2);
                ldsm4(af[i], aB + off);
            }
            #pragma unroll
            for (int j4 = 0; j4 < 2; j4++) {
                uint32_t off = (uint32_t)((j4 * 16 * SMS + ks * 16) * 2);
                uint32_t bh4[4];
                ldsm4(bh4, bB + off);
                mma16816(acc[0][2*j4],   af[0], &bh4[0]);
                mma16816(acc[0][2*j4+1], af[0], &bh4[2]);
                mma16816(acc[1][2*j4],   af[1], &bh4[0]);
                mma16816(acc[1][2*j4+1], af[1], &bh4[2]);
            }
        }
    }

    // Epilogue. d0=(r,c), d1=(r,c+1), d2=(r+8,c), d3=(r+8,c+1);
    // r = lane>>2, c = (lane&3)*2.
    #pragma unroll
    for (int i = 0; i < 2; i++) {
        int gm = m0 + warpM * 32 + i * 16 + (lane >> 2);
        #pragma unroll
        for (int j = 0; j < 4; j++) {
            int gn = n0 + warpN * 32 + j * 8 + (lane & 3) * 2;
            float* d = acc[i][j];
            if (L1) {
                #pragma unroll
                for (int half = 0; half < 2; half++) {
                    int r = gm + half * 8;
                    float v0 = elu1(d[half * 2 + 0]);
                    float v1 = elu1(d[half * 2 + 1]);
                    __half2 hp = __halves2half2(__float2half_rn(v0), __float2half_rn(v1));
                    *reinterpret_cast<uint32_t*>(Ch + (size_t)r * ldc + gn) = *(uint32_t*)&hp;
                }
            } else {
                size_t off0 = (size_t)gm * ldc + gn;
                size_t off1 = (size_t)(gm + 8) * ldc + gn;
                *reinterpret_cast<float2*>(Cf + off0) = make_float2(d[0], d[1]);
                *reinterpret_cast<float2*>(Cf + off1) = make_float2(d[2], d[3]);
            }
        }
    }

    // Producer publishes completion for its sample.
    if (L1) {
        __syncthreads();
        __threadfence();
        if (tid == 0) atomicAdd(&g_cnt[s], 1);
    }
}

// ---------------------------------------------------------------------------
// Launch
// Inputs: x [1024,512], z [10,8], Wa [10,8], Wb [10,10], Wc [1048576,10], samples
// Output: y [10, 1024, 512] fp32
// ---------------------------------------------------------------------------
extern "C" void kernel_launch(void* const* d_in, const int* in_sizes, int n_in,
                              void* d_out, int out_size) {
    const float* x  = (const float*)d_in[0];
    const float* z  = (const float*)d_in[1];
    const float* Wa = (const float*)d_in[2];
    const float* Wb = (const float*)d_in[3];
    const float* Wc = (const float*)d_in[4];
    float* out = (float*)d_out;
    (void)in_sizes; (void)n_in; (void)out_size;

    __half *xh, *th, *ah;
    cudaGetSymbolAddress((void**)&xh, g_xh);
    cudaGetSymbolAddress((void**)&th, g_th);
    cudaGetSymbolAddress((void**)&ah, g_ah);

    static bool attr_done = false;
    if (!attr_done) {
        cudaFuncSetAttribute(fused_gemm_kernel,
                             cudaFuncAttributeMaxDynamicSharedMemorySize, SMEM_BYTES);
        attr_done = true;
    }

    hyper_trunk_kernel<<<1, 128>>>(z, Wa, Wb);
    xconv_kernel<<<(BATCH * IN_DIM / 4 + 255) / 256, 256>>>(x);
    theta_kernel<<<(NPARAMS / 2 + 255) / 256, 256>>>(Wc);

    fused_gemm_kernel<<<L1_CTAS + L2_CTAS, 256, SMEM_BYTES>>>(
        xh, th, ah, out);
}